// round 2
// baseline (speedup 1.0000x reference)
#include <cuda_runtime.h>

// Integrate-and-fire scan, TBN layout.
//   m_t = v_{t-1} + x_t ;  y_t = (m_t >= 1) ;  v_t = m_t - y_t
// Columns (b,n) independent -> one thread per 4 columns (float4), scan T=32 in regs.

#define T_STEPS 32

__global__ void __launch_bounds__(256) if_scan_kernel(
    const float4* __restrict__ x, float4* __restrict__ y, int bn4)
{
    int i = blockIdx.x * blockDim.x + threadIdx.x;
    if (i >= bn4) return;

    float4 v = make_float4(0.f, 0.f, 0.f, 0.f);

    #pragma unroll
    for (int t = 0; t < T_STEPS; t++) {
        long idx = (long)t * bn4 + i;
        float4 m = x[idx];
        m.x += v.x; m.y += v.y; m.z += v.z; m.w += v.w;

        float4 s;
        s.x = (m.x >= 1.0f) ? 1.0f : 0.0f;
        s.y = (m.y >= 1.0f) ? 1.0f : 0.0f;
        s.z = (m.z >= 1.0f) ? 1.0f : 0.0f;
        s.w = (m.w >= 1.0f) ? 1.0f : 0.0f;

        v.x = m.x - s.x;
        v.y = m.y - s.y;
        v.z = m.z - s.z;
        v.w = m.w - s.w;

        y[idx] = s;
    }
}

extern "C" void kernel_launch(void* const* d_in, const int* in_sizes, int n_in,
                              void* d_out, int out_size)
{
    const float4* x = (const float4*)d_in[0];
    float4* y = (float4*)d_out;

    int total = in_sizes[0];           // T*B*N
    int bn = total / T_STEPS;          // B*N columns
    int bn4 = bn / 4;                  // float4 columns

    int threads = 256;
    int blocks = (bn4 + threads - 1) / threads;
    if_scan_kernel<<<blocks, threads>>>(x, y, bn4);
}